// round 5
// baseline (speedup 1.0000x reference)
#include <cuda_runtime.h>

#define N_NODES 50000
#define N_EDGES 600000
#define D 128

#define COUNT_BLOCKS ((N_EDGES + 255) / 256)         // 2344
#define FILL_BLOCKS  COUNT_BLOCKS
#define GEMM_BLOCKS  ((N_NODES + 31) / 32)           // 1563
#define GEMM_A 500
#define GEMM_B 550
#define GEMM_C (GEMM_BLOCKS - GEMM_A - GEMM_B)       // 513

// ---- scratch (device globals: no allocation allowed) ----
__device__ int   g_deg[N_NODES];
__device__ int   g_off[N_NODES + 1];
__device__ int   g_cur[N_NODES];
__device__ float g_inv[N_NODES];
__device__ int   g_csr_src[N_EDGES];
__device__ float g_y[(size_t)N_NODES * D];           // y = x @ W
__device__ int   g_is64;

__device__ __forceinline__ int load_idx(const void* p, int e, int is64) {
    if (is64) return (int)((const long long*)p)[e];
    return ((const int*)p)[e];
}

// ---- packed f32x2 helpers (FFMA2 reachable only via PTX) ----
__device__ __forceinline__ unsigned long long pk2(float lo, float hi) {
    unsigned long long r;
    asm("mov.b64 %0, {%1, %2};" : "=l"(r) : "f"(lo), "f"(hi));
    return r;
}
__device__ __forceinline__ unsigned long long ffma2(unsigned long long a,
                                                    unsigned long long b,
                                                    unsigned long long c) {
    unsigned long long d;
    asm("fma.rn.f32x2 %0, %1, %2, %3;" : "=l"(d) : "l"(a), "l"(b), "l"(c));
    return d;
}
__device__ __forceinline__ float2 unpk2(unsigned long long v) {
    float2 f;
    asm("mov.b64 {%0, %1}, %2;" : "=f"(f.x), "=f"(f.y) : "l"(v));
    return f;
}

// ---- GEMM tile body: y[row0..row0+31] = x[row0..row0+31] @ W ----
// 256 threads: thread (tr = t>>5, tc = t&31) computes rows tr*4..+3, cols tc*4..+3.
__device__ __forceinline__ void gemm_body(int blk, const float* __restrict__ x,
                                          const float* __restrict__ W) {
    __shared__ float As[32 * D];
    int row0 = blk * 32;
    int t = threadIdx.x;

    for (int i = t; i < 32 * (D / 4); i += 256) {
        int r = i >> 5;
        int c4 = i & 31;
        int row = row0 + r;
        float4 v = (row < N_NODES)
                       ? ((const float4*)(x + (size_t)row * D))[c4]
                       : make_float4(0.f, 0.f, 0.f, 0.f);
        ((float4*)As)[i] = v;
    }
    __syncthreads();

    int tc = t & 31;
    int tr = t >> 5;

    unsigned long long acc[4][2];
    #pragma unroll
    for (int r = 0; r < 4; r++) { acc[r][0] = 0ULL; acc[r][1] = 0ULL; }

    #pragma unroll 4
    for (int k = 0; k < D; k++) {
        ulonglong2 w = ((const ulonglong2*)(W + (size_t)k * D))[tc];
        #pragma unroll
        for (int r = 0; r < 4; r++) {
            float a = As[(tr * 4 + r) * D + k];
            unsigned long long a2 = pk2(a, a);
            acc[r][0] = ffma2(a2, w.x, acc[r][0]);
            acc[r][1] = ffma2(a2, w.y, acc[r][1]);
        }
    }

    #pragma unroll
    for (int r = 0; r < 4; r++) {
        int row = row0 + tr * 4 + r;
        if (row < N_NODES) {
            float2 lo = unpk2(acc[r][0]);
            float2 hi = unpk2(acc[r][1]);
            float4 o = make_float4(lo.x, lo.y, hi.x, hi.y);
            ((float4*)(g_y + (size_t)row * D))[tc] = o;
        }
    }
}

// ---- Launch 1: zero degrees + int64/int32 detection ----
// (JAX without x64 downcasts int64->int32; detect by checking the odd 32-bit
// words of src — all zero iff the data is 8-byte little-endian values < 2^31.)
__global__ void k_init(const unsigned int* __restrict__ src_words) {
    int i = blockIdx.x * blockDim.x + threadIdx.x;
    if (i < N_NODES) g_deg[i] = 0;
    if (blockIdx.x == 0 && threadIdx.x == 0) {
        int all0 = 1;
        #pragma unroll
        for (int j = 1; j < 128; j += 2) all0 &= (src_words[j] == 0u);
        g_is64 = all0;
    }
}

// ---- Launch 2: degree histogram  ||  GEMM chunk A ----
__global__ void __launch_bounds__(256) k_p1(const void* __restrict__ dst,
                                            const float* __restrict__ x,
                                            const float* __restrict__ W) {
    if (blockIdx.x < COUNT_BLOCKS) {
        int is64 = g_is64;
        int e = blockIdx.x * 256 + threadIdx.x;
        if (e < N_EDGES) {
            int d = load_idx(dst, e, is64);
            atomicAdd(&g_deg[d], 1);
        }
    } else {
        gemm_body(blockIdx.x - COUNT_BLOCKS, x, W);
    }
}

// ---- Launch 3: single-block scan (block 0)  ||  GEMM chunk B ----
__global__ void __launch_bounds__(256) k_p2(const float* __restrict__ x,
                                            const float* __restrict__ W) {
    if (blockIdx.x == 0) {
        const int C = (N_NODES + 255) / 256;  // 196 per thread
        int t = threadIdx.x;
        int base = t * C;
        int sum = 0;
        #pragma unroll 4
        for (int i = 0; i < C; i++) {
            int idx = base + i;
            if (idx < N_NODES) sum += g_deg[idx];
        }
        __shared__ int part[256];
        part[t] = sum;
        __syncthreads();
        for (int ofs = 1; ofs < 256; ofs <<= 1) {
            int v = (t >= ofs) ? part[t - ofs] : 0;
            __syncthreads();
            part[t] += v;
            __syncthreads();
        }
        int run = part[t] - sum;  // exclusive prefix
        for (int i = 0; i < C; i++) {
            int idx = base + i;
            if (idx < N_NODES) {
                int d = g_deg[idx];
                g_off[idx] = run;
                g_cur[idx] = run;
                g_inv[idx] = rsqrtf((float)d);
                run += d;
                if (idx == N_NODES - 1) g_off[N_NODES] = run;
            }
        }
    } else {
        gemm_body(GEMM_A + (int)blockIdx.x - 1, x, W);
    }
}

// ---- Launch 4: CSR fill  ||  GEMM chunk C ----
__global__ void __launch_bounds__(256) k_p3(const void* __restrict__ src,
                                            const void* __restrict__ dst,
                                            const float* __restrict__ x,
                                            const float* __restrict__ W) {
    if (blockIdx.x < FILL_BLOCKS) {
        int is64 = g_is64;
        int e = blockIdx.x * 256 + threadIdx.x;
        if (e < N_EDGES) {
            int d = load_idx(dst, e, is64);
            int s = load_idx(src, e, is64);
            int pos = atomicAdd(&g_cur[d], 1);
            g_csr_src[pos] = s;
        }
    } else {
        gemm_body(GEMM_A + GEMM_B + (int)blockIdx.x - FILL_BLOCKS, x, W);
    }
}

// ---- Launch 5: gather-aggregate + epilogue ----
// out[d] = inv[d] * sum_{s in N(d)} inv[s] * y[s]  +  deg[d] * b
__global__ void __launch_bounds__(256) k_agg(const float* __restrict__ b,
                                             float* __restrict__ out) {
    int w    = (blockIdx.x * blockDim.x + threadIdx.x) >> 5;
    int lane = threadIdx.x & 31;
    if (w >= N_NODES) return;
    int beg = g_off[w];
    int end = g_off[w + 1];

    float4 acc = make_float4(0.f, 0.f, 0.f, 0.f);
    int e = beg;
    for (; e + 2 <= end; e += 2) {
        int s0 = g_csr_src[e];
        int s1 = g_csr_src[e + 1];
        float c0 = g_inv[s0];
        float c1 = g_inv[s1];
        float4 v0 = ((const float4*)(g_y + (size_t)s0 * D))[lane];
        float4 v1 = ((const float4*)(g_y + (size_t)s1 * D))[lane];
        acc.x += c0 * v0.x + c1 * v1.x;
        acc.y += c0 * v0.y + c1 * v1.y;
        acc.z += c0 * v0.z + c1 * v1.z;
        acc.w += c0 * v0.w + c1 * v1.w;
    }
    if (e < end) {
        int s = g_csr_src[e];
        float c = g_inv[s];
        float4 v = ((const float4*)(g_y + (size_t)s * D))[lane];
        acc.x += c * v.x; acc.y += c * v.y; acc.z += c * v.z; acc.w += c * v.w;
    }

    float invd = g_inv[w];
    float degf = (float)g_deg[w];
    float4 bv = ((const float4*)b)[lane];
    float4 o;
    o.x = invd * acc.x + degf * bv.x;
    o.y = invd * acc.y + degf * bv.y;
    o.z = invd * acc.z + degf * bv.z;
    o.w = invd * acc.w + degf * bv.w;
    ((float4*)(out + (size_t)w * D))[lane] = o;
}

extern "C" void kernel_launch(void* const* d_in, const int* in_sizes, int n_in,
                              void* d_out, int out_size) {
    const float* x   = (const float*)d_in[0];
    const void*  src = d_in[1];
    const void*  dst = d_in[2];
    const float* W   = (const float*)d_in[3];
    const float* b   = (const float*)d_in[4];
    float* out = (float*)d_out;

    (void)in_sizes; (void)n_in; (void)out_size;

    k_init<<<(N_NODES + 255) / 256, 256>>>((const unsigned int*)src);
    k_p1<<<COUNT_BLOCKS + GEMM_A, 256>>>(dst, x, W);
    k_p2<<<1 + GEMM_B, 256>>>(x, W);
    k_p3<<<FILL_BLOCKS + GEMM_C, 256>>>(src, dst, x, W);
    k_agg<<<(N_NODES * 32 + 255) / 256, 256>>>(b, out);
}

// round 6
// speedup vs baseline: 1.8533x; 1.8533x over previous
#include <cuda_runtime.h>

#define N_NODES 50000
#define N_EDGES 600000
#define D 128

#define NB 296                       // persistent blocks = 148 SMs * 2 (co-resident)
#define NC 96                        // CSR-builder blocks
#define NG (NB - NC)                 // 200 GEMM blocks
#define CT 3                         // nodes per CSR-thread in scan phases (96*256*3 >= 50000)
#define GEMM_TILES ((N_NODES + 31) / 32)   // 1563

// ---- scratch (device globals: no allocation allowed) ----
__device__ int   g_deg[N_NODES];
__device__ int   g_off[N_NODES + 1];
__device__ int   g_cur[N_NODES];
__device__ float g_inv[N_NODES];
__device__ int   g_csr_src[N_EDGES];
__device__ float g_y[(size_t)N_NODES * D];    // y = x @ W
__device__ int   g_is64;
__device__ int   g_part[NC];
__device__ int   g_pscan[NC];
__device__ int   g_bar[8];                    // monotonic per launch; reset by k_init

__device__ __forceinline__ int load_idx(const void* p, int e, int is64) {
    if (is64) return (int)((const long long*)p)[e];
    return ((const int*)p)[e];
}

// Device barrier: monotonic counter per slot, reset to 0 by k_init each launch
// (stream-ordered before k_main, so no cross-launch reset race).
__device__ __forceinline__ void barwait(int id, int target) {
    __syncthreads();
    if (threadIdx.x == 0) {
        __threadfence();                       // release my writes
        atomicAdd(&g_bar[id], 1);
        while (atomicAdd(&g_bar[id], 0) < target) __nanosleep(64);
    }
    __syncthreads();
    __threadfence();                           // acquire others' writes
}

// ---- packed f32x2 helpers (FFMA2 reachable only via PTX) ----
__device__ __forceinline__ unsigned long long pk2(float lo, float hi) {
    unsigned long long r;
    asm("mov.b64 %0, {%1, %2};" : "=l"(r) : "f"(lo), "f"(hi));
    return r;
}
__device__ __forceinline__ unsigned long long ffma2(unsigned long long a,
                                                    unsigned long long b,
                                                    unsigned long long c) {
    unsigned long long d;
    asm("fma.rn.f32x2 %0, %1, %2, %3;" : "=l"(d) : "l"(a), "l"(b), "l"(c));
    return d;
}
__device__ __forceinline__ float2 unpk2(unsigned long long v) {
    float2 f;
    asm("mov.b64 {%0, %1}, %2;" : "=f"(f.x), "=f"(f.y) : "l"(v));
    return f;
}

__shared__ float s_As[32 * D];     // GEMM A tile (G blocks); idle on C blocks
__shared__ int   s_scan[256];      // block scan buffer (C blocks)

// ---- GEMM tile: y[row0..row0+31] = x[row0..row0+31] @ W (thread = 4x4 micro-tile)
__device__ __forceinline__ void gemm_body(int blk, const float* __restrict__ x,
                                          const float* __restrict__ W) {
    int row0 = blk * 32;
    int t = threadIdx.x;

    for (int i = t; i < 32 * (D / 4); i += 256) {
        int r = i >> 5;
        int c4 = i & 31;
        int row = row0 + r;
        float4 v = (row < N_NODES)
                       ? ((const float4*)(x + (size_t)row * D))[c4]
                       : make_float4(0.f, 0.f, 0.f, 0.f);
        ((float4*)s_As)[i] = v;
    }
    __syncthreads();

    int tc = t & 31;
    int tr = t >> 5;

    unsigned long long acc[4][2];
    #pragma unroll
    for (int r = 0; r < 4; r++) { acc[r][0] = 0ULL; acc[r][1] = 0ULL; }

    #pragma unroll 4
    for (int k = 0; k < D; k++) {
        ulonglong2 w = ((const ulonglong2*)(W + (size_t)k * D))[tc];
        #pragma unroll
        for (int r = 0; r < 4; r++) {
            float a = s_As[(tr * 4 + r) * D + k];
            unsigned long long a2 = pk2(a, a);
            acc[r][0] = ffma2(a2, w.x, acc[r][0]);
            acc[r][1] = ffma2(a2, w.y, acc[r][1]);
        }
    }

    #pragma unroll
    for (int r = 0; r < 4; r++) {
        int row = row0 + tr * 4 + r;
        if (row < N_NODES) {
            float2 lo = unpk2(acc[r][0]);
            float2 hi = unpk2(acc[r][1]);
            ((float4*)(g_y + (size_t)row * D))[tc] = make_float4(lo.x, lo.y, hi.x, hi.y);
        }
    }
    __syncthreads();   // protect s_As before next tile
}

// ---- Launch 1: zero degrees + barrier counters + int64/int32 detection ----
// (JAX without x64 downcasts int64->int32; detect by checking the odd 32-bit
// words of src — all zero iff the data is 8-byte little-endian values < 2^31.)
__global__ void k_init(const unsigned int* __restrict__ src_words) {
    int i = blockIdx.x * blockDim.x + threadIdx.x;
    if (i < N_NODES) g_deg[i] = 0;
    if (i < 8) g_bar[i] = 0;
    if (i == 0) {
        int all0 = 1;
        #pragma unroll
        for (int j = 1; j < 128; j += 2) all0 &= (src_words[j] == 0u);
        g_is64 = all0;
    }
}

// ---- Launch 2: persistent kernel.
// Blocks [0,NC): count -> scan -> fill (group barriers 0..3).
// Blocks [NC,NB): GEMM tiles.
// All blocks: global barrier (slot 4) -> gather-aggregate + epilogue.
__global__ void __launch_bounds__(256, 2)
k_main(const float* __restrict__ x, const void* __restrict__ src,
       const void* __restrict__ dst, const float* __restrict__ W,
       const float* __restrict__ b, float* __restrict__ out) {
    int blk = blockIdx.x;
    int t = threadIdx.x;

    if (blk < NC) {
        // ===== CSR chain =====
        int is64 = g_is64;

        // Phase C1: degree histogram
        for (int e = blk * 256 + t; e < N_EDGES; e += NC * 256) {
            int d = load_idx(dst, e, is64);
            atomicAdd(&g_deg[d], 1);
        }
        barwait(0, NC);

        // Phase C2: per-thread partial sums (contiguous CT nodes each)
        int base = (blk * 256 + t) * CT;
        int dcache[CT];
        int mysum = 0;
        #pragma unroll
        for (int i = 0; i < CT; i++) {
            int idx = base + i;
            dcache[i] = (idx < N_NODES) ? g_deg[idx] : 0;
            mysum += dcache[i];
        }
        s_scan[t] = mysum;
        __syncthreads();
        #pragma unroll
        for (int ofs = 1; ofs < 256; ofs <<= 1) {
            int v = (t >= ofs) ? s_scan[t - ofs] : 0;
            __syncthreads();
            s_scan[t] += v;
            __syncthreads();
        }
        int excl = s_scan[t] - mysum;
        if (t == 255) g_part[blk] = s_scan[255];
        barwait(1, NC);

        // Phase C3: warp-scan of the NC block partials (block 0, warp 0)
        if (blk == 0 && t < 32) {
            int carry = 0;
            #pragma unroll
            for (int seg = 0; seg < NC / 32; seg++) {
                int orig = g_part[seg * 32 + t];
                int v = orig;
                #pragma unroll
                for (int o = 1; o < 32; o <<= 1) {
                    int u = __shfl_up_sync(0xFFFFFFFFu, v, o);
                    if (t >= o) v += u;
                }
                g_pscan[seg * 32 + t] = carry + v - orig;   // exclusive
                carry += __shfl_sync(0xFFFFFFFFu, v, 31);
            }
        }
        barwait(2, NC);

        // Phase C4: write offsets, cursors, rsqrt(deg)
        int run = g_pscan[blk] + excl;
        #pragma unroll
        for (int i = 0; i < CT; i++) {
            int idx = base + i;
            if (idx < N_NODES) {
                g_off[idx] = run;
                g_cur[idx] = run;
                g_inv[idx] = rsqrtf((float)dcache[i]);
                run += dcache[i];
                if (idx == N_NODES - 1) g_off[N_NODES] = run;
            }
        }
        barwait(3, NC);

        // Phase C5: CSR fill via atomic cursors
        for (int e = blk * 256 + t; e < N_EDGES; e += NC * 256) {
            int d = load_idx(dst, e, is64);
            int s = load_idx(src, e, is64);
            int pos = atomicAdd(&g_cur[d], 1);
            g_csr_src[pos] = s;
        }
    } else {
        // ===== GEMM: y = x @ W (independent of the graph) =====
        for (int tile = blk - NC; tile < GEMM_TILES; tile += NG)
            gemm_body(tile, x, W);
    }

    // ===== join =====
    barwait(4, NB);

    // ===== aggregate: out[d] = inv[d]*sum_{s in N(d)} inv[s]*y[s] + deg[d]*b =====
    int lane = t & 31;
    int gw = blk * 8 + (t >> 5);
    float4 bv = ((const float4*)b)[lane];

    for (int w = gw; w < N_NODES; w += NB * 8) {
        int beg = g_off[w];
        int end = g_off[w + 1];

        float4 acc = make_float4(0.f, 0.f, 0.f, 0.f);
        int e = beg;
        for (; e + 2 <= end; e += 2) {
            int s0 = g_csr_src[e];
            int s1 = g_csr_src[e + 1];
            float c0 = g_inv[s0];
            float c1 = g_inv[s1];
            float4 v0 = ((const float4*)(g_y + (size_t)s0 * D))[lane];
            float4 v1 = ((const float4*)(g_y + (size_t)s1 * D))[lane];
            acc.x += c0 * v0.x + c1 * v1.x;
            acc.y += c0 * v0.y + c1 * v1.y;
            acc.z += c0 * v0.z + c1 * v1.z;
            acc.w += c0 * v0.w + c1 * v1.w;
        }
        if (e < end) {
            int s = g_csr_src[e];
            float c = g_inv[s];
            float4 v = ((const float4*)(g_y + (size_t)s * D))[lane];
            acc.x += c * v.x; acc.y += c * v.y; acc.z += c * v.z; acc.w += c * v.w;
        }

        float invd = g_inv[w];
        float degf = (float)g_deg[w];
        float4 o;
        o.x = invd * acc.x + degf * bv.x;
        o.y = invd * acc.y + degf * bv.y;
        o.z = invd * acc.z + degf * bv.z;
        o.w = invd * acc.w + degf * bv.w;
        ((float4*)(out + (size_t)w * D))[lane] = o;
    }
}

extern "C" void kernel_launch(void* const* d_in, const int* in_sizes, int n_in,
                              void* d_out, int out_size) {
    const float* x   = (const float*)d_in[0];
    const void*  src = d_in[1];
    const void*  dst = d_in[2];
    const float* W   = (const float*)d_in[3];
    const float* b   = (const float*)d_in[4];
    float* out = (float*)d_out;

    (void)in_sizes; (void)n_in; (void)out_size;

    k_init<<<(N_NODES + 255) / 256, 256>>>((const unsigned int*)src);
    k_main<<<NB, 256>>>(x, src, dst, W, b, out);
}

// round 7
// speedup vs baseline: 2.0341x; 1.0976x over previous
#include <cuda_runtime.h>

#define N_NODES 50000
#define N_EDGES 600000
#define D 128

#define NB 296                       // persistent blocks = 148 SMs * 2 (co-resident)
#define NC 96                        // CSR-builder blocks
#define NG (NB - NC)                 // 200 GEMM blocks
#define CT 3                         // nodes per CSR-thread in scan phases (96*256*3 >= 50000)
#define GEMM_TILES ((N_NODES + 31) / 32)   // 1563

// ---- scratch (device globals: no allocation allowed) ----
__device__ int   g_deg[N_NODES];
__device__ int   g_off[N_NODES + 1];
__device__ int   g_cur[N_NODES];
__device__ float g_inv[N_NODES];
__device__ int   g_csr_src[N_EDGES];
__device__ float g_y[(size_t)N_NODES * D];    // y = x @ W
__device__ int   g_is64;
__device__ int   g_part[NC];
__device__ int   g_pscan[NC];
__device__ int   g_bar[8];                    // monotonic per launch; reset by k_init

__device__ __forceinline__ int load_idx(const void* p, int e, int is64) {
    if (is64) return (int)((const long long*)p)[e];
    return ((const int*)p)[e];
}

// Device barrier among the NC CSR blocks only (monotonic counters, reset by k_init;
// k_init is stream-ordered before k_main so there is no cross-launch reset race).
__device__ __forceinline__ void barwait(int id, int target) {
    __syncthreads();
    if (threadIdx.x == 0) {
        __threadfence();                       // release my writes
        atomicAdd(&g_bar[id], 1);
        while (atomicAdd(&g_bar[id], 0) < target) __nanosleep(64);
    }
    __syncthreads();
    __threadfence();                           // acquire others' writes
}

// ---- packed f32x2 helpers (FFMA2 reachable only via PTX) ----
__device__ __forceinline__ unsigned long long pk2(float lo, float hi) {
    unsigned long long r;
    asm("mov.b64 %0, {%1, %2};" : "=l"(r) : "f"(lo), "f"(hi));
    return r;
}
__device__ __forceinline__ unsigned long long ffma2(unsigned long long a,
                                                    unsigned long long b,
                                                    unsigned long long c) {
    unsigned long long d;
    asm("fma.rn.f32x2 %0, %1, %2, %3;" : "=l"(d) : "l"(a), "l"(b), "l"(c));
    return d;
}
__device__ __forceinline__ float2 unpk2(unsigned long long v) {
    float2 f;
    asm("mov.b64 {%0, %1}, %2;" : "=f"(f.x), "=f"(f.y) : "l"(v));
    return f;
}

__shared__ float s_As[32 * D];     // GEMM A tile (G blocks); idle on C blocks
__shared__ int   s_scan[256];      // block scan buffer (C blocks)

// ---- GEMM tile: y[row0..row0+31] = x[row0..row0+31] @ W (thread = 4x4 micro-tile)
__device__ __forceinline__ void gemm_body(int blk, const float* __restrict__ x,
                                          const float* __restrict__ W) {
    int row0 = blk * 32;
    int t = threadIdx.x;

    for (int i = t; i < 32 * (D / 4); i += 256) {
        int r = i >> 5;
        int c4 = i & 31;
        int row = row0 + r;
        float4 v = (row < N_NODES)
                       ? ((const float4*)(x + (size_t)row * D))[c4]
                       : make_float4(0.f, 0.f, 0.f, 0.f);
        ((float4*)s_As)[i] = v;
    }
    __syncthreads();

    int tc = t & 31;
    int tr = t >> 5;

    unsigned long long acc[4][2];
    #pragma unroll
    for (int r = 0; r < 4; r++) { acc[r][0] = 0ULL; acc[r][1] = 0ULL; }

    #pragma unroll 4
    for (int k = 0; k < D; k++) {
        ulonglong2 w = ((const ulonglong2*)(W + (size_t)k * D))[tc];
        #pragma unroll
        for (int r = 0; r < 4; r++) {
            float a = s_As[(tr * 4 + r) * D + k];
            unsigned long long a2 = pk2(a, a);
            acc[r][0] = ffma2(a2, w.x, acc[r][0]);
            acc[r][1] = ffma2(a2, w.y, acc[r][1]);
        }
    }

    #pragma unroll
    for (int r = 0; r < 4; r++) {
        int row = row0 + tr * 4 + r;
        if (row < N_NODES) {
            float2 lo = unpk2(acc[r][0]);
            float2 hi = unpk2(acc[r][1]);
            ((float4*)(g_y + (size_t)row * D))[tc] = make_float4(lo.x, lo.y, hi.x, hi.y);
        }
    }
    __syncthreads();   // protect s_As before next tile
}

// ---- Launch 1: zero degrees + barrier counters + int64/int32 detection ----
// (JAX without x64 downcasts int64->int32; detect by checking the odd 32-bit
// words of src — all zero iff the data is 8-byte little-endian values < 2^31.)
__global__ void k_init(const unsigned int* __restrict__ src_words) {
    int i = blockIdx.x * blockDim.x + threadIdx.x;
    if (i < N_NODES) g_deg[i] = 0;
    if (i < 8) g_bar[i] = 0;
    if (i == 0) {
        int all0 = 1;
        #pragma unroll
        for (int j = 1; j < 128; j += 2) all0 &= (src_words[j] == 0u);
        g_is64 = all0;
    }
}

// ---- Launch 2: persistent kernel (build + GEMM only; blocks exit when done).
// Blocks [0,NC): count -> scan -> fill (group barriers 0..3).
// Blocks [NC,NB): GEMM tiles. The kernel boundary is the global join.
__global__ void __launch_bounds__(256, 2)
k_main(const float* __restrict__ x, const void* __restrict__ src,
       const void* __restrict__ dst, const float* __restrict__ W) {
    int blk = blockIdx.x;
    int t = threadIdx.x;

    if (blk < NC) {
        // ===== CSR chain =====
        int is64 = g_is64;

        // Phase C1: degree histogram
        for (int e = blk * 256 + t; e < N_EDGES; e += NC * 256) {
            int d = load_idx(dst, e, is64);
            atomicAdd(&g_deg[d], 1);
        }
        barwait(0, NC);

        // Phase C2: per-thread partial sums (contiguous CT nodes each)
        int base = (blk * 256 + t) * CT;
        int dcache[CT];
        int mysum = 0;
        #pragma unroll
        for (int i = 0; i < CT; i++) {
            int idx = base + i;
            dcache[i] = (idx < N_NODES) ? g_deg[idx] : 0;
            mysum += dcache[i];
        }
        s_scan[t] = mysum;
        __syncthreads();
        #pragma unroll
        for (int ofs = 1; ofs < 256; ofs <<= 1) {
            int v = (t >= ofs) ? s_scan[t - ofs] : 0;
            __syncthreads();
            s_scan[t] += v;
            __syncthreads();
        }
        int excl = s_scan[t] - mysum;
        if (t == 255) g_part[blk] = s_scan[255];
        barwait(1, NC);

        // Phase C3: warp-scan of the NC block partials (block 0, warp 0)
        if (blk == 0 && t < 32) {
            int carry = 0;
            #pragma unroll
            for (int seg = 0; seg < NC / 32; seg++) {
                int orig = g_part[seg * 32 + t];
                int v = orig;
                #pragma unroll
                for (int o = 1; o < 32; o <<= 1) {
                    int u = __shfl_up_sync(0xFFFFFFFFu, v, o);
                    if (t >= o) v += u;
                }
                g_pscan[seg * 32 + t] = carry + v - orig;   // exclusive
                carry += __shfl_sync(0xFFFFFFFFu, v, 31);
            }
        }
        barwait(2, NC);

        // Phase C4: write offsets, cursors, rsqrt(deg)
        int run = g_pscan[blk] + excl;
        #pragma unroll
        for (int i = 0; i < CT; i++) {
            int idx = base + i;
            if (idx < N_NODES) {
                g_off[idx] = run;
                g_cur[idx] = run;
                g_inv[idx] = rsqrtf((float)dcache[i]);
                run += dcache[i];
                if (idx == N_NODES - 1) g_off[N_NODES] = run;
            }
        }
        barwait(3, NC);

        // Phase C5: CSR fill via atomic cursors
        for (int e = blk * 256 + t; e < N_EDGES; e += NC * 256) {
            int d = load_idx(dst, e, is64);
            int s = load_idx(src, e, is64);
            int pos = atomicAdd(&g_cur[d], 1);
            g_csr_src[pos] = s;
        }
    } else {
        // ===== GEMM: y = x @ W (independent of the graph) =====
        for (int tile = blk - NC; tile < GEMM_TILES; tile += NG)
            gemm_body(tile, x, W);
    }
}

// ---- Launch 3: gather-aggregate + epilogue (high occupancy: no smem, lean regs).
// One warp per node, each lane owns 4 contiguous feature cols (float4).
// out[d] = inv[d] * sum_{s in N(d)} inv[s] * y[s]  +  deg[d] * b
__global__ void __launch_bounds__(256)
k_agg(const float* __restrict__ b, float* __restrict__ out) {
    int w    = (blockIdx.x * blockDim.x + threadIdx.x) >> 5;
    int lane = threadIdx.x & 31;
    if (w >= N_NODES) return;
    int beg = g_off[w];
    int end = g_off[w + 1];

    float4 acc = make_float4(0.f, 0.f, 0.f, 0.f);
    int e = beg;

    // unroll-4: batch the index+coeff loads, then issue 4 independent row loads (MLP>=4)
    for (; e + 4 <= end; e += 4) {
        int s0 = g_csr_src[e];
        int s1 = g_csr_src[e + 1];
        int s2 = g_csr_src[e + 2];
        int s3 = g_csr_src[e + 3];
        float c0 = g_inv[s0];
        float c1 = g_inv[s1];
        float c2 = g_inv[s2];
        float c3 = g_inv[s3];
        float4 v0 = ((const float4*)(g_y + (size_t)s0 * D))[lane];
        float4 v1 = ((const float4*)(g_y + (size_t)s1 * D))[lane];
        float4 v2 = ((const float4*)(g_y + (size_t)s2 * D))[lane];
        float4 v3 = ((const float4*)(g_y + (size_t)s3 * D))[lane];
        acc.x += c0 * v0.x + c1 * v1.x + c2 * v2.x + c3 * v3.x;
        acc.y += c0 * v0.y + c1 * v1.y + c2 * v2.y + c3 * v3.y;
        acc.z += c0 * v0.z + c1 * v1.z + c2 * v2.z + c3 * v3.z;
        acc.w += c0 * v0.w + c1 * v1.w + c2 * v2.w + c3 * v3.w;
    }
    for (; e < end; e++) {
        int s = g_csr_src[e];
        float c = g_inv[s];
        float4 v = ((const float4*)(g_y + (size_t)s * D))[lane];
        acc.x += c * v.x; acc.y += c * v.y; acc.z += c * v.z; acc.w += c * v.w;
    }

    float invd = g_inv[w];
    float degf = (float)g_deg[w];
    float4 bv = ((const float4*)b)[lane];
    float4 o;
    o.x = invd * acc.x + degf * bv.x;
    o.y = invd * acc.y + degf * bv.y;
    o.z = invd * acc.z + degf * bv.z;
    o.w = invd * acc.w + degf * bv.w;
    ((float4*)(out + (size_t)w * D))[lane] = o;
}

extern "C" void kernel_launch(void* const* d_in, const int* in_sizes, int n_in,
                              void* d_out, int out_size) {
    const float* x   = (const float*)d_in[0];
    const void*  src = d_in[1];
    const void*  dst = d_in[2];
    const float* W   = (const float*)d_in[3];
    const float* b   = (const float*)d_in[4];
    float* out = (float*)d_out;

    (void)in_sizes; (void)n_in; (void)out_size;

    k_init<<<(N_NODES + 255) / 256, 256>>>((const unsigned int*)src);
    k_main<<<NB, 256>>>(x, src, dst, W);
    k_agg<<<(N_NODES * 32 + 255) / 256, 256>>>(b, out);
}

// round 8
// speedup vs baseline: 2.4794x; 1.2189x over previous
#include <cuda_runtime.h>

#define N_NODES 50000
#define N_EDGES 600000
#define D 128

#define NB 444                       // persistent blocks = 148 SMs * 3 (co-resident)
#define NC 96                        // CSR-builder blocks (first wave guaranteed)
#define CT 3                         // nodes per CSR-thread in scan phases (96*256*3 >= 50000)
#define GEMM_TILES ((N_NODES + 31) / 32)   // 1563

// ---- scratch (device globals: no allocation allowed) ----
__device__ int   g_deg[N_NODES];
__device__ int   g_off[N_NODES + 1];
__device__ int   g_cur[N_NODES];
__device__ float g_inv[N_NODES];
__device__ int   g_csr_src[N_EDGES];
__device__ float g_y[(size_t)N_NODES * D];    // y = x @ W
__device__ int   g_is64;
__device__ int   g_part[NC];
__device__ int   g_pscan[NC];
__device__ int   g_bar[8];                    // monotonic per launch; reset by k_init
__device__ int   g_tile;                      // GEMM work-stealing cursor; reset by k_init

__device__ __forceinline__ int load_idx(const void* p, int e, int is64) {
    if (is64) return (int)((const long long*)p)[e];
    return ((const int*)p)[e];
}

// Device barrier among the NC CSR blocks only (monotonic counters, reset by k_init;
// k_init is stream-ordered before k_main so there is no cross-launch reset race).
__device__ __forceinline__ void barwait(int id, int target) {
    __syncthreads();
    if (threadIdx.x == 0) {
        __threadfence();                       // release my writes
        atomicAdd(&g_bar[id], 1);
        while (atomicAdd(&g_bar[id], 0) < target) __nanosleep(32);
    }
    __syncthreads();
    __threadfence();                           // acquire others' writes
}

// ---- packed f32x2 helpers (FFMA2 reachable only via PTX) ----
__device__ __forceinline__ unsigned long long pk2(float lo, float hi) {
    unsigned long long r;
    asm("mov.b64 %0, {%1, %2};" : "=l"(r) : "f"(lo), "f"(hi));
    return r;
}
__device__ __forceinline__ unsigned long long ffma2(unsigned long long a,
                                                    unsigned long long b,
                                                    unsigned long long c) {
    unsigned long long d;
    asm("fma.rn.f32x2 %0, %1, %2, %3;" : "=l"(d) : "l"(a), "l"(b), "l"(c));
    return d;
}
__device__ __forceinline__ float2 unpk2(unsigned long long v) {
    float2 f;
    asm("mov.b64 {%0, %1}, %2;" : "=f"(f.x), "=f"(f.y) : "l"(v));
    return f;
}

__shared__ float s_As[32 * D];     // GEMM A tile
__shared__ int   s_scan[256];      // block scan buffer (CSR blocks)
__shared__ int   s_tile;           // stolen tile id broadcast

// ---- GEMM tile: y[row0..row0+31] = x[row0..row0+31] @ W (thread = 4x4 micro-tile)
__device__ __forceinline__ void gemm_body(int blk, const float* __restrict__ x,
                                          const float* __restrict__ W) {
    int row0 = blk * 32;
    int t = threadIdx.x;

    for (int i = t; i < 32 * (D / 4); i += 256) {
        int r = i >> 5;
        int c4 = i & 31;
        int row = row0 + r;
        float4 v = (row < N_NODES)
                       ? ((const float4*)(x + (size_t)row * D))[c4]
                       : make_float4(0.f, 0.f, 0.f, 0.f);
        ((float4*)s_As)[i] = v;
    }
    __syncthreads();

    int tc = t & 31;
    int tr = t >> 5;

    unsigned long long acc[4][2];
    #pragma unroll
    for (int r = 0; r < 4; r++) { acc[r][0] = 0ULL; acc[r][1] = 0ULL; }

    #pragma unroll 4
    for (int k = 0; k < D; k++) {
        ulonglong2 w = ((const ulonglong2*)(W + (size_t)k * D))[tc];
        #pragma unroll
        for (int r = 0; r < 4; r++) {
            float a = s_As[(tr * 4 + r) * D + k];
            unsigned long long a2 = pk2(a, a);
            acc[r][0] = ffma2(a2, w.x, acc[r][0]);
            acc[r][1] = ffma2(a2, w.y, acc[r][1]);
        }
    }

    #pragma unroll
    for (int r = 0; r < 4; r++) {
        int row = row0 + tr * 4 + r;
        if (row < N_NODES) {
            float2 lo = unpk2(acc[r][0]);
            float2 hi = unpk2(acc[r][1]);
            ((float4*)(g_y + (size_t)row * D))[tc] = make_float4(lo.x, lo.y, hi.x, hi.y);
        }
    }
    __syncthreads();   // protect s_As before next tile
}

// Work-stealing GEMM loop: grab tiles from the global cursor until drained.
__device__ __forceinline__ void gemm_steal(const float* __restrict__ x,
                                           const float* __restrict__ W) {
    for (;;) {
        __syncthreads();                       // protect s_tile reuse
        if (threadIdx.x == 0) s_tile = atomicAdd(&g_tile, 1);
        __syncthreads();
        int tile = s_tile;
        if (tile >= GEMM_TILES) break;
        gemm_body(tile, x, W);
    }
}

// ---- Launch 1: zero degrees + control words + int64/int32 detection ----
// (JAX without x64 downcasts int64->int32; detect by checking the odd 32-bit
// words of src — all zero iff the data is 8-byte little-endian values < 2^31.)
__global__ void k_init(const unsigned int* __restrict__ src_words) {
    int i = blockIdx.x * blockDim.x + threadIdx.x;
    if (i < N_NODES) g_deg[i] = 0;
    if (i < 8) g_bar[i] = 0;
    if (i == 8) g_tile = 0;
    if (i == 0) {
        int all0 = 1;
        #pragma unroll
        for (int j = 1; j < 128; j += 2) all0 &= (src_words[j] == 0u);
        g_is64 = all0;
    }
}

// ---- Launch 2: persistent kernel (build + GEMM, work-conserving).
// Blocks [0,NC): count -> scan -> fill (group barriers 0..3), then JOIN the
// GEMM stealing loop. Blocks [NC,NB): GEMM stealing from the start.
// The kernel boundary is the global join before aggregation.
__global__ void __launch_bounds__(256, 3)
k_main(const float* __restrict__ x, const void* __restrict__ src,
       const void* __restrict__ dst, const float* __restrict__ W) {
    int blk = blockIdx.x;
    int t = threadIdx.x;

    if (blk < NC) {
        // ===== CSR chain =====
        int is64 = g_is64;

        // Phase C1: degree histogram
        for (int e = blk * 256 + t; e < N_EDGES; e += NC * 256) {
            int d = load_idx(dst, e, is64);
            atomicAdd(&g_deg[d], 1);
        }
        barwait(0, NC);

        // Phase C2: per-thread partial sums (contiguous CT nodes each)
        int base = (blk * 256 + t) * CT;
        int dcache[CT];
        int mysum = 0;
        #pragma unroll
        for (int i = 0; i < CT; i++) {
            int idx = base + i;
            dcache[i] = (idx < N_NODES) ? g_deg[idx] : 0;
            mysum += dcache[i];
        }
        s_scan[t] = mysum;
        __syncthreads();
        #pragma unroll
        for (int ofs = 1; ofs < 256; ofs <<= 1) {
            int v = (t >= ofs) ? s_scan[t - ofs] : 0;
            __syncthreads();
            s_scan[t] += v;
            __syncthreads();
        }
        int excl = s_scan[t] - mysum;
        if (t == 255) g_part[blk] = s_scan[255];
        barwait(1, NC);

        // Phase C3: warp-scan of the NC block partials (block 0, warp 0)
        if (blk == 0 && t < 32) {
            int carry = 0;
            #pragma unroll
            for (int seg = 0; seg < NC / 32; seg++) {
                int orig = g_part[seg * 32 + t];
                int v = orig;
                #pragma unroll
                for (int o = 1; o < 32; o <<= 1) {
                    int u = __shfl_up_sync(0xFFFFFFFFu, v, o);
                    if (t >= o) v += u;
                }
                g_pscan[seg * 32 + t] = carry + v - orig;   // exclusive
                carry += __shfl_sync(0xFFFFFFFFu, v, 31);
            }
        }
        barwait(2, NC);

        // Phase C4: write offsets, cursors, rsqrt(deg)
        int run = g_pscan[blk] + excl;
        #pragma unroll
        for (int i = 0; i < CT; i++) {
            int idx = base + i;
            if (idx < N_NODES) {
                g_off[idx] = run;
                g_cur[idx] = run;
                g_inv[idx] = rsqrtf((float)dcache[i]);
                run += dcache[i];
                if (idx == N_NODES - 1) g_off[N_NODES] = run;
            }
        }
        barwait(3, NC);

        // Phase C5: CSR fill via atomic cursors
        for (int e = blk * 256 + t; e < N_EDGES; e += NC * 256) {
            int d = load_idx(dst, e, is64);
            int s = load_idx(src, e, is64);
            int pos = atomicAdd(&g_cur[d], 1);
            g_csr_src[pos] = s;
        }
        // done building -> help finish the GEMM
        gemm_steal(x, W);
    } else {
        // ===== GEMM: y = x @ W (independent of the graph) =====
        gemm_steal(x, W);
    }
}

// ---- Launch 3: gather-aggregate + epilogue (high occupancy: no smem, lean regs).
// One warp per node, each lane owns 4 contiguous feature cols (float4).
// out[d] = inv[d] * sum_{s in N(d)} inv[s] * y[s]  +  deg[d] * b
__global__ void __launch_bounds__(256)
k_agg(const float* __restrict__ b, float* __restrict__ out) {
    int w    = (blockIdx.x * blockDim.x + threadIdx.x) >> 5;
    int lane = threadIdx.x & 31;
    if (w >= N_NODES) return;
    int beg = g_off[w];
    int end = g_off[w + 1];

    float4 acc = make_float4(0.f, 0.f, 0.f, 0.f);
    int e = beg;

    // unroll-4: batch the index+coeff loads, then issue 4 independent row loads (MLP>=4)
    for (; e + 4 <= end; e += 4) {
        int s0 = g_csr_src[e];
        int s1 = g_csr_src[e + 1];
        int s2 = g_csr_src[e + 2];
        int s3 = g_csr_src[e + 3];
        float c0 = g_inv[s0];
        float c1 = g_inv[s1];
        float c2 = g_inv[s2];
        float c3 = g_inv[s3];
        float4 v0 = ((const float4*)(g_y + (size_t)s0 * D))[lane];
        float4 v1 = ((const float4*)(g_y + (size_t)s1 * D))[lane];
        float4 v2 = ((const float4*)(g_y + (size_t)s2 * D))[lane];
        float4 v3 = ((const float4*)(g_y + (size_t)s3 * D))[lane];
        acc.x += c0 * v0.x + c1 * v1.x + c2 * v2.x + c3 * v3.x;
        acc.y += c0 * v0.y + c1 * v1.y + c2 * v2.y + c3 * v3.y;
        acc.z += c0 * v0.z + c1 * v1.z + c2 * v2.z + c3 * v3.z;
        acc.w += c0 * v0.w + c1 * v1.w + c2 * v2.w + c3 * v3.w;
    }
    for (; e < end; e++) {
        int s = g_csr_src[e];
        float c = g_inv[s];
        float4 v = ((const float4*)(g_y + (size_t)s * D))[lane];
        acc.x += c * v.x; acc.y += c * v.y; acc.z += c * v.z; acc.w += c * v.w;
    }

    float invd = g_inv[w];
    float degf = (float)g_deg[w];
    float4 bv = ((const float4*)b)[lane];
    float4 o;
    o.x = invd * acc.x + degf * bv.x;
    o.y = invd * acc.y + degf * bv.y;
    o.z = invd * acc.z + degf * bv.z;
    o.w = invd * acc.w + degf * bv.w;
    ((float4*)(out + (size_t)w * D))[lane] = o;
}

extern "C" void kernel_launch(void* const* d_in, const int* in_sizes, int n_in,
                              void* d_out, int out_size) {
    const float* x   = (const float*)d_in[0];
    const void*  src = d_in[1];
    const void*  dst = d_in[2];
    const float* W   = (const float*)d_in[3];
    const float* b   = (const float*)d_in[4];
    float* out = (float*)d_out;

    (void)in_sizes; (void)n_in; (void)out_size;

    k_init<<<(N_NODES + 255) / 256, 256>>>((const unsigned int*)src);
    k_main<<<NB, 256>>>(x, src, dst, W);
    k_agg<<<(N_NODES * 32 + 255) / 256, 256>>>(b, out);
}

// round 10
// speedup vs baseline: 2.5196x; 1.0162x over previous
#include <cuda_runtime.h>

#define N_NODES 50000
#define N_EDGES 600000
#define D 128

#define NB 296                       // persistent blocks = 148 SMs * 2 (co-resident)
#define NC 96                        // CSR-builder blocks (first wave guaranteed)
#define CT 3                         // nodes per CSR-thread in scan phases (96*256*3 >= 50000)
#define TILE_R 64                    // GEMM rows per tile
#define GEMM_TILES ((N_NODES + TILE_R - 1) / TILE_R)   // 782

// ---- scratch (device globals: no allocation allowed) ----
__device__ int   g_deg[N_NODES];
__device__ int   g_off[N_NODES + 1];
__device__ int   g_cur[N_NODES];
__device__ float g_inv[N_NODES];
__device__ int   g_csr_src[N_EDGES];
__device__ float g_y[(size_t)N_NODES * D];    // y = x @ W
__device__ int   g_part[NC];
__device__ int   g_pscan[NC];
__device__ int   g_bar[8];                    // monotonic per launch; reset by k_agg
__device__ int   g_tile;                      // GEMM work-steal cursor; reset by k_agg

__device__ __forceinline__ int load_idx(const void* p, int e, int is64) {
    if (is64) return (int)((const long long*)p)[e];
    return ((const int*)p)[e];
}

// Device barrier among the NC CSR blocks only (monotonic counters; reset by the
// trailing k_agg launch, which is stream-ordered after k_main -> no reset race).
__device__ __forceinline__ void barwait(int id, int target) {
    __syncthreads();
    if (threadIdx.x == 0) {
        __threadfence();                       // release my writes
        atomicAdd(&g_bar[id], 1);
        while (atomicAdd(&g_bar[id], 0) < target) __nanosleep(32);
    }
    __syncthreads();
    __threadfence();                           // acquire others' writes
}

// ---- packed f32x2 helpers (FFMA2 reachable only via PTX) ----
__device__ __forceinline__ unsigned long long pk2(float lo, float hi) {
    unsigned long long r;
    asm("mov.b64 %0, {%1, %2};" : "=l"(r) : "f"(lo), "f"(hi));
    return r;
}
__device__ __forceinline__ unsigned long long ffma2(unsigned long long a,
                                                    unsigned long long b,
                                                    unsigned long long c) {
    unsigned long long d;
    asm("fma.rn.f32x2 %0, %1, %2, %3;" : "=l"(d) : "l"(a), "l"(b), "l"(c));
    return d;
}
__device__ __forceinline__ float2 unpk2(unsigned long long v) {
    float2 f;
    asm("mov.b64 {%0, %1}, %2;" : "=f"(f.x), "=f"(f.y) : "l"(v));
    return f;
}

// ---- GEMM tile: y[row0..row0+63] = x[row0..row0+63] @ W.
// A staged TRANSPOSED in smem (As[k][r]) so each thread's 8 row-values for a
// given k are contiguous -> 2x LDS.128 yields row-PAIR-packed u64 operands for
// FFMA2 with no packing MOVs. As is __align__(16) so the 128-bit LDS is legal.
// Accumulators pack row pairs; only w needs broadcast-packing (8 MOVs per
// k-iter serving 16 FFMA2).
__device__ __forceinline__ void gemm_body(int blk, const float* __restrict__ x,
                                          const float* __restrict__ W) {
    __shared__ __align__(16) float As[D * TILE_R];   // As[k*64 + r], 32 KB
    int row0 = blk * TILE_R;
    int t = threadIdx.x;

    // stage x tile transposed: 64 rows x 32 float4-cols, 2048 float4s / 256 thr
    for (int i = t; i < TILE_R * (D / 4); i += 256) {
        int r  = i & (TILE_R - 1);
        int c4 = i >> 6;
        int row = row0 + r;
        float4 v = (row < N_NODES)
                       ? ((const float4*)(x + (size_t)row * D))[c4]
                       : make_float4(0.f, 0.f, 0.f, 0.f);
        As[(c4 * 4 + 0) * TILE_R + r] = v.x;
        As[(c4 * 4 + 1) * TILE_R + r] = v.y;
        As[(c4 * 4 + 2) * TILE_R + r] = v.z;
        As[(c4 * 4 + 3) * TILE_R + r] = v.w;
    }
    __syncthreads();

    int tc = t & 31;   // col group: cols 4*tc .. 4*tc+3
    int tr = t >> 5;   // row group: rows 8*tr .. 8*tr+7

    unsigned long long acc[4][4];              // [rowpair][col]
    #pragma unroll
    for (int rp = 0; rp < 4; rp++)
        #pragma unroll
        for (int c = 0; c < 4; c++) acc[rp][c] = 0ULL;

    const float* as_base = As + tr * 8;        // (k*64 + tr*8)*4B: 32B-multiple offsets

    #pragma unroll 4
    for (int k = 0; k < D; k++) {
        float4 w = ((const float4*)(W + (size_t)k * D))[tc];
        unsigned long long w2[4];
        w2[0] = pk2(w.x, w.x);
        w2[1] = pk2(w.y, w.y);
        w2[2] = pk2(w.z, w.z);
        w2[3] = pk2(w.w, w.w);
        ulonglong2 A0 = *(const ulonglong2*)(as_base + k * TILE_R);      // rows 0-3
        ulonglong2 A1 = *(const ulonglong2*)(as_base + k * TILE_R + 4);  // rows 4-7
        #pragma unroll
        for (int c = 0; c < 4; c++) {
            acc[0][c] = ffma2(A0.x, w2[c], acc[0][c]);
            acc[1][c] = ffma2(A0.y, w2[c], acc[1][c]);
            acc[2][c] = ffma2(A1.x, w2[c], acc[2][c]);
            acc[3][c] = ffma2(A1.y, w2[c], acc[3][c]);
        }
    }

    #pragma unroll
    for (int rp = 0; rp < 4; rp++) {
        float2 c0 = unpk2(acc[rp][0]);
        float2 c1 = unpk2(acc[rp][1]);
        float2 c2 = unpk2(acc[rp][2]);
        float2 c3 = unpk2(acc[rp][3]);
        int r_lo = row0 + tr * 8 + rp * 2;
        int r_hi = r_lo + 1;
        if (r_lo < N_NODES)
            ((float4*)(g_y + (size_t)r_lo * D))[tc] = make_float4(c0.x, c1.x, c2.x, c3.x);
        if (r_hi < N_NODES)
            ((float4*)(g_y + (size_t)r_hi * D))[tc] = make_float4(c0.y, c1.y, c2.y, c3.y);
    }
    __syncthreads();   // protect As before next tile
}

// Work-stealing GEMM loop: grab tiles from the global cursor until drained.
__device__ __forceinline__ void gemm_steal(const float* __restrict__ x,
                                           const float* __restrict__ W) {
    __shared__ int s_tile;
    for (;;) {
        __syncthreads();                       // protect s_tile reuse
        if (threadIdx.x == 0) s_tile = atomicAdd(&g_tile, 1);
        __syncthreads();
        int tile = s_tile;
        if (tile >= GEMM_TILES) break;
        gemm_body(tile, x, W);
    }
}

// ---- Launch 1: persistent kernel (zero + build + GEMM, work-conserving).
// Blocks [0,NC): zero -> count -> scan -> fill (group barriers 0..4), then JOIN
// the GEMM stealing loop. Blocks [NC,NB): GEMM stealing from the start.
// The kernel boundary is the global join before aggregation.
__global__ void __launch_bounds__(256, 2)
k_main(const float* __restrict__ x, const void* __restrict__ src,
       const void* __restrict__ dst, const float* __restrict__ W) {
    int blk = blockIdx.x;
    int t = threadIdx.x;

    if (blk < NC) {
        __shared__ int s_scan[256];
        __shared__ int s_ok;

        // int64/int32 detection, block-local. (JAX without x64 downcasts
        // int64->int32; the odd 32-bit words of src are all zero iff the data
        // is 8-byte little-endian values < 2^31.)
        if (t == 0) s_ok = 1;
        __syncthreads();
        if (t < 64 && ((const unsigned int*)src)[2 * t + 1] != 0u) s_ok = 0;
        // Phase C0: zero the degree array (interleaved with detection)
        for (int i = blk * 256 + t; i < N_NODES; i += NC * 256) g_deg[i] = 0;
        __syncthreads();
        int is64 = s_ok;
        barwait(0, NC);

        // Phase C1: degree histogram
        for (int e = blk * 256 + t; e < N_EDGES; e += NC * 256) {
            int d = load_idx(dst, e, is64);
            atomicAdd(&g_deg[d], 1);
        }
        barwait(1, NC);

        // Phase C2: per-thread partial sums (contiguous CT nodes each)
        int base = (blk * 256 + t) * CT;
        int dcache[CT];
        int mysum = 0;
        #pragma unroll
        for (int i = 0; i < CT; i++) {
            int idx = base + i;
            dcache[i] = (idx < N_NODES) ? g_deg[idx] : 0;
            mysum += dcache[i];
        }
        s_scan[t] = mysum;
        __syncthreads();
        #pragma unroll
        for (int ofs = 1; ofs < 256; ofs <<= 1) {
            int v = (t >= ofs) ? s_scan[t - ofs] : 0;
            __syncthreads();
            s_scan[t] += v;
            __syncthreads();
        }
        int excl = s_scan[t] - mysum;
        if (t == 255) g_part[blk] = s_scan[255];
        barwait(2, NC);

        // Phase C3: warp-scan of the NC block partials (block 0, warp 0)
        if (blk == 0 && t < 32) {
            int carry = 0;
            #pragma unroll
            for (int seg = 0; seg < NC / 32; seg++) {
                int orig = g_part[seg * 32 + t];
                int v = orig;
                #pragma unroll
                for (int o = 1; o < 32; o <<= 1) {
                    int u = __shfl_up_sync(0xFFFFFFFFu, v, o);
                    if (t >= o) v += u;
                }
                g_pscan[seg * 32 + t] = carry + v - orig;   // exclusive
                carry += __shfl_sync(0xFFFFFFFFu, v, 31);
            }
        }
        barwait(3, NC);

        // Phase C4: write offsets, cursors, rsqrt(deg)
        int run = g_pscan[blk] + excl;
        #pragma unroll
        for (int i = 0; i < CT; i++) {
            int idx = base + i;
            if (idx < N_NODES) {
                g_off[idx] = run;
                g_cur[idx] = run;
                g_inv[idx] = rsqrtf((float)dcache[i]);
                run += dcache[i];
                if (idx == N_NODES - 1) g_off[N_NODES] = run;
            }
        }
        barwait(4, NC);

        // Phase C5: CSR fill via atomic cursors
        for (int e = blk * 256 + t; e < N_EDGES; e += NC * 256) {
            int d = load_idx(dst, e, is64);
            int s = load_idx(src, e, is64);
            int pos = atomicAdd(&g_cur[d], 1);
            g_csr_src[pos] = s;
        }
        // done building -> help finish the GEMM
        gemm_steal(x, W);
    } else {
        // ===== GEMM: y = x @ W (independent of the graph) =====
        gemm_steal(x, W);
    }
}

// ---- Launch 2: gather-aggregate + epilogue (no smem, lean regs, high occ).
// One warp per node, each lane owns 4 contiguous feature cols (float4).
// out[d] = inv[d] * sum_{s in N(d)} inv[s] * y[s]  +  deg[d] * b
// Also resets the barrier/tile counters for the next replay (stream-ordered
// after k_main, so no race with the polls).
__global__ void __launch_bounds__(256)
k_agg(const float* __restrict__ b, float* __restrict__ out) {
    if (blockIdx.x == 0) {
        if (threadIdx.x < 8) g_bar[threadIdx.x] = 0;
        if (threadIdx.x == 8) g_tile = 0;
    }

    int w    = (blockIdx.x * blockDim.x + threadIdx.x) >> 5;
    int lane = threadIdx.x & 31;
    if (w >= N_NODES) return;
    int beg = g_off[w];
    int end = g_off[w + 1];

    float4 acc = make_float4(0.f, 0.f, 0.f, 0.f);
    int e = beg;

    // unroll-4: batch the index+coeff loads, then issue 4 independent row loads (MLP>=4)
    for (; e + 4 <= end; e += 4) {
        int s0 = g_csr_src[e];
        int s1 = g_csr_src[e + 1];
        int s2 = g_csr_src[e + 2];
        int s3 = g_csr_src[e + 3];
        float c0 = g_inv[s0];
        float c1 = g_inv[s1];
        float c2 = g_inv[s2];
        float c3 = g_inv[s3];
        float4 v0 = ((const float4*)(g_y + (size_t)s0 * D))[lane];
        float4 v1 = ((const float4*)(g_y + (size_t)s1 * D))[lane];
        float4 v2 = ((const float4*)(g_y + (size_t)s2 * D))[lane];
        float4 v3 = ((const float4*)(g_y + (size_t)s3 * D))[lane];
        acc.x += c0 * v0.x + c1 * v1.x + c2 * v2.x + c3 * v3.x;
        acc.y += c0 * v0.y + c1 * v1.y + c2 * v2.y + c3 * v3.y;
        acc.z += c0 * v0.z + c1 * v1.z + c2 * v2.z + c3 * v3.z;
        acc.w += c0 * v0.w + c1 * v1.w + c2 * v2.w + c3 * v3.w;
    }
    for (; e < end; e++) {
        int s = g_csr_src[e];
        float c = g_inv[s];
        float4 v = ((const float4*)(g_y + (size_t)s * D))[lane];
        acc.x += c * v.x; acc.y += c * v.y; acc.z += c * v.z; acc.w += c * v.w;
    }

    float invd = g_inv[w];
    float degf = (float)g_deg[w];
    float4 bv = ((const float4*)b)[lane];
    float4 o;
    o.x = invd * acc.x + degf * bv.x;
    o.y = invd * acc.y + degf * bv.y;
    o.z = invd * acc.z + degf * bv.z;
    o.w = invd * acc.w + degf * bv.w;
    ((float4*)(out + (size_t)w * D))[lane] = o;
}

extern "C" void kernel_launch(void* const* d_in, const int* in_sizes, int n_in,
                              void* d_out, int out_size) {
    const float* x   = (const float*)d_in[0];
    const void*  src = d_in[1];
    const void*  dst = d_in[2];
    const float* W   = (const float*)d_in[3];
    const float* b   = (const float*)d_in[4];
    float* out = (float*)d_out;

    (void)in_sizes; (void)n_in; (void)out_size;

    k_main<<<NB, 256>>>(x, src, dst, W);
    k_agg<<<(N_NODES * 32 + 255) / 256, 256>>>(b, out);
}

// round 11
// speedup vs baseline: 2.8672x; 1.1379x over previous
#include <cuda_runtime.h>
#include <cuda_fp16.h>

#define N_NODES 50000
#define N_EDGES 600000
#define D 128

#define NB 444                       // persistent blocks = 148 SMs * 3 (co-resident)
#define NC 96                        // CSR-builder blocks (first wave guaranteed)
#define CT 3                         // nodes per CSR-thread in scan phases (96*256*3 >= 50000)
#define TILE_R 64                    // GEMM rows per tile
#define GEMM_TILES ((N_NODES + TILE_R - 1) / TILE_R)   // 782

// ---- scratch (device globals: no allocation allowed) ----
__device__ int    g_deg[N_NODES];
__device__ int    g_off[N_NODES + 1];
__device__ int    g_cur[N_NODES];
__device__ float  g_inv[N_NODES];
__device__ int    g_csr_src[N_EDGES];
__device__ __half g_yh[(size_t)N_NODES * D];  // y = x @ W, fp16 (12.8 MB: L2-resident)
__device__ int    g_part[NC];
__device__ int    g_pscan[NC];
__device__ int    g_bar[8];                   // monotonic per launch; reset by k_agg
__device__ int    g_tile;                     // GEMM work-steal cursor; reset by k_agg

__device__ __forceinline__ int load_idx(const void* p, int e, int is64) {
    if (is64) return (int)((const long long*)p)[e];
    return ((const int*)p)[e];
}

// Device barrier among the NC CSR blocks only (monotonic counters; reset by the
// trailing k_agg launch, which is stream-ordered after k_main -> no reset race).
__device__ __forceinline__ void barwait(int id, int target) {
    __syncthreads();
    if (threadIdx.x == 0) {
        __threadfence();                       // release my writes
        atomicAdd(&g_bar[id], 1);
        while (atomicAdd(&g_bar[id], 0) < target) __nanosleep(32);
    }
    __syncthreads();
    __threadfence();                           // acquire others' writes
}

// ---- packed f32x2 helpers (FFMA2 reachable only via PTX) ----
__device__ __forceinline__ unsigned long long pk2(float lo, float hi) {
    unsigned long long r;
    asm("mov.b64 %0, {%1, %2};" : "=l"(r) : "f"(lo), "f"(hi));
    return r;
}
__device__ __forceinline__ unsigned long long ffma2(unsigned long long a,
                                                    unsigned long long b,
                                                    unsigned long long c) {
    unsigned long long d;
    asm("fma.rn.f32x2 %0, %1, %2, %3;" : "=l"(d) : "l"(a), "l"(b), "l"(c));
    return d;
}
__device__ __forceinline__ float2 unpk2(unsigned long long v) {
    float2 f;
    asm("mov.b64 {%0, %1}, %2;" : "=f"(f.x), "=f"(f.y) : "l"(v));
    return f;
}

// ---- GEMM tile: y[row0..row0+63] = x[row0..row0+63] @ W, stored as fp16.
// A staged TRANSPOSED in smem (As[k][r]) so each thread's 8 row-values for a
// given k are contiguous -> 2x LDS.128 yields row-PAIR-packed u64 operands for
// FFMA2 with no packing MOVs. As is __align__(16) so the 128-bit LDS is legal.
__device__ __forceinline__ void gemm_body(int blk, const float* __restrict__ x,
                                          const float* __restrict__ W) {
    __shared__ __align__(16) float As[D * TILE_R];   // As[k*64 + r], 32 KB
    int row0 = blk * TILE_R;
    int t = threadIdx.x;

    // stage x tile transposed: 64 rows x 32 float4-cols, 2048 float4s / 256 thr
    for (int i = t; i < TILE_R * (D / 4); i += 256) {
        int r  = i & (TILE_R - 1);
        int c4 = i >> 6;
        int row = row0 + r;
        float4 v = (row < N_NODES)
                       ? ((const float4*)(x + (size_t)row * D))[c4]
                       : make_float4(0.f, 0.f, 0.f, 0.f);
        As[(c4 * 4 + 0) * TILE_R + r] = v.x;
        As[(c4 * 4 + 1) * TILE_R + r] = v.y;
        As[(c4 * 4 + 2) * TILE_R + r] = v.z;
        As[(c4 * 4 + 3) * TILE_R + r] = v.w;
    }
    __syncthreads();

    int tc = t & 31;   // col group: cols 4*tc .. 4*tc+3
    int tr = t >> 5;   // row group: rows 8*tr .. 8*tr+7

    unsigned long long acc[4][4];              // [rowpair][col]
    #pragma unroll
    for (int rp = 0; rp < 4; rp++)
        #pragma unroll
        for (int c = 0; c < 4; c++) acc[rp][c] = 0ULL;

    const float* as_base = As + tr * 8;        // (k*64 + tr*8)*4B: 32B-multiple offsets

    #pragma unroll 4
    for (int k = 0; k < D; k++) {
        float4 w = ((const float4*)(W + (size_t)k * D))[tc];
        unsigned long long w2[4];
        w2[0] = pk2(w.x, w.x);
        w2[1] = pk2(w.y, w.y);
        w2[2] = pk2(w.z, w.z);
        w2[3] = pk2(w.w, w.w);
        ulonglong2 A0 = *(const ulonglong2*)(as_base + k * TILE_R);      // rows 0-3
        ulonglong2 A1 = *(const ulonglong2*)(as_base + k * TILE_R + 4);  // rows 4-7
        #pragma unroll
        for (int c = 0; c < 4; c++) {
            acc[0][c] = ffma2(A0.x, w2[c], acc[0][c]);
            acc[1][c] = ffma2(A0.y, w2[c], acc[1][c]);
            acc[2][c] = ffma2(A1.x, w2[c], acc[2][c]);
            acc[3][c] = ffma2(A1.y, w2[c], acc[3][c]);
        }
    }

    #pragma unroll
    for (int rp = 0; rp < 4; rp++) {
        float2 c0 = unpk2(acc[rp][0]);
        float2 c1 = unpk2(acc[rp][1]);
        float2 c2 = unpk2(acc[rp][2]);
        float2 c3 = unpk2(acc[rp][3]);
        int r_lo = row0 + tr * 8 + rp * 2;
        int r_hi = r_lo + 1;
        if (r_lo < N_NODES) {
            __half2 p0 = __floats2half2_rn(c0.x, c1.x);
            __half2 p1 = __floats2half2_rn(c2.x, c3.x);
            uint2 u;
            u.x = *(unsigned int*)&p0;
            u.y = *(unsigned int*)&p1;
            ((uint2*)(g_yh + (size_t)r_lo * D))[tc] = u;
        }
        if (r_hi < N_NODES) {
            __half2 p0 = __floats2half2_rn(c0.y, c1.y);
            __half2 p1 = __floats2half2_rn(c2.y, c3.y);
            uint2 u;
            u.x = *(unsigned int*)&p0;
            u.y = *(unsigned int*)&p1;
            ((uint2*)(g_yh + (size_t)r_hi * D))[tc] = u;
        }
    }
    __syncthreads();   // protect As before next tile
}

// Work-stealing GEMM loop: grab tiles from the global cursor until drained.
__device__ __forceinline__ void gemm_steal(const float* __restrict__ x,
                                           const float* __restrict__ W) {
    __shared__ int s_tile;
    for (;;) {
        __syncthreads();                       // protect s_tile reuse
        if (threadIdx.x == 0) s_tile = atomicAdd(&g_tile, 1);
        __syncthreads();
        int tile = s_tile;
        if (tile >= GEMM_TILES) break;
        gemm_body(tile, x, W);
    }
}

// ---- Launch 1: persistent kernel (zero + build + GEMM, work-conserving).
// Blocks [0,NC): zero -> count -> scan -> fill (group barriers 0..4), then JOIN
// the GEMM stealing loop. Blocks [NC,NB): GEMM stealing from the start.
// The kernel boundary is the global join before aggregation.
__global__ void __launch_bounds__(256, 3)
k_main(const float* __restrict__ x, const void* __restrict__ src,
       const void* __restrict__ dst, const float* __restrict__ W) {
    int blk = blockIdx.x;
    int t = threadIdx.x;

    if (blk < NC) {
        __shared__ int s_scan[256];
        __shared__ int s_ok;

        // int64/int32 detection, block-local. (JAX without x64 downcasts
        // int64->int32; the odd 32-bit words of src are all zero iff the data
        // is 8-byte little-endian values < 2^31.)
        if (t == 0) s_ok = 1;
        __syncthreads();
        if (t < 64 && ((const unsigned int*)src)[2 * t + 1] != 0u) s_ok = 0;
        // Phase C0: zero the degree array (interleaved with detection)
        for (int i = blk * 256 + t; i < N_NODES; i += NC * 256) g_deg[i] = 0;
        __syncthreads();
        int is64 = s_ok;
        barwait(0, NC);

        // Phase C1: degree histogram
        for (int e = blk * 256 + t; e < N_EDGES; e += NC * 256) {
            int d = load_idx(dst, e, is64);
            atomicAdd(&g_deg[d], 1);
        }
        barwait(1, NC);

        // Phase C2: per-thread partial sums (contiguous CT nodes each)
        int base = (blk * 256 + t) * CT;
        int dcache[CT];
        int mysum = 0;
        #pragma unroll
        for (int i = 0; i < CT; i++) {
            int idx = base + i;
            dcache[i] = (idx < N_NODES) ? g_deg[idx] : 0;
            mysum += dcache[i];
        }
        s_scan[t] = mysum;
        __syncthreads();
        #pragma unroll
        for (int ofs = 1; ofs < 256; ofs <<= 1) {
            int v = (t >= ofs) ? s_scan[t - ofs] : 0;
            __syncthreads();
            s_scan[t] += v;
            __syncthreads();
        }
        int excl = s_scan[t] - mysum;
        if (t == 255) g_part[blk] = s_scan[255];
        barwait(2, NC);

        // Phase C3: warp-scan of the NC block partials (block 0, warp 0)
        if (blk == 0 && t < 32) {
            int carry = 0;
            #pragma unroll
            for (int seg = 0; seg < NC / 32; seg++) {
                int orig = g_part[seg * 32 + t];
                int v = orig;
                #pragma unroll
                for (int o = 1; o < 32; o <<= 1) {
                    int u = __shfl_up_sync(0xFFFFFFFFu, v, o);
                    if (t >= o) v += u;
                }
                g_pscan[seg * 32 + t] = carry + v - orig;   // exclusive
                carry += __shfl_sync(0xFFFFFFFFu, v, 31);
            }
        }
        barwait(3, NC);

        // Phase C4: write offsets, cursors, rsqrt(deg)
        int run = g_pscan[blk] + excl;
        #pragma unroll
        for (int i = 0; i < CT; i++) {
            int idx = base + i;
            if (idx < N_NODES) {
                g_off[idx] = run;
                g_cur[idx] = run;
                g_inv[idx] = rsqrtf((float)dcache[i]);
                run += dcache[i];
                if (idx == N_NODES - 1) g_off[N_NODES] = run;
            }
        }
        barwait(4, NC);

        // Phase C5: CSR fill via atomic cursors
        for (int e = blk * 256 + t; e < N_EDGES; e += NC * 256) {
            int d = load_idx(dst, e, is64);
            int s = load_idx(src, e, is64);
            int pos = atomicAdd(&g_cur[d], 1);
            g_csr_src[pos] = s;
        }
        // done building -> help finish the GEMM
        gemm_steal(x, W);
    } else {
        // ===== GEMM: y = x @ W (independent of the graph) =====
        gemm_steal(x, W);
    }
}

// ---- Launch 2: gather-aggregate + epilogue (fp16 y gather, fp32 accumulate).
// One warp per node; each lane owns 4 cols (4 halves = 8B load per neighbor row).
// out[d] = inv[d] * sum_{s in N(d)} inv[s] * y[s]  +  deg[d] * b
// Also resets the barrier/tile counters for the next replay (stream-ordered
// after k_main, so no race with the polls).
__global__ void __launch_bounds__(256)
k_agg(const float* __restrict__ b, float* __restrict__ out) {
    if (blockIdx.x == 0) {
        if (threadIdx.x < 8) g_bar[threadIdx.x] = 0;
        if (threadIdx.x == 8) g_tile = 0;
    }

    int w    = (blockIdx.x * blockDim.x + threadIdx.x) >> 5;
    int lane = threadIdx.x & 31;
    if (w >= N_NODES) return;
    int beg = g_off[w];
    int end = g_off[w + 1];

    float4 acc = make_float4(0.f, 0.f, 0.f, 0.f);
    int e = beg;

    // unroll-4: batch index+coeff loads, then 4 independent row loads (MLP>=4)
    for (; e + 4 <= end; e += 4) {
        int s0 = g_csr_src[e];
        int s1 = g_csr_src[e + 1];
        int s2 = g_csr_src[e + 2];
        int s3 = g_csr_src[e + 3];
        float c0 = g_inv[s0];
        float c1 = g_inv[s1];
        float c2 = g_inv[s2];
        float c3 = g_inv[s3];
        uint2 u0 = ((const uint2*)(g_yh + (size_t)s0 * D))[lane];
        uint2 u1 = ((const uint2*)(g_yh + (size_t)s1 * D))[lane];
        uint2 u2 = ((const uint2*)(g_yh + (size_t)s2 * D))[lane];
        uint2 u3 = ((const uint2*)(g_yh + (size_t)s3 * D))[lane];
        float2 a0 = __half22float2(*(__half2*)&u0.x), b0 = __half22float2(*(__half2*)&u0.y);
        float2 a1 = __half22float2(*(__half2*)&u1.x), b1 = __half22float2(*(__half2*)&u1.y);
        float2 a2 = __half22float2(*(__half2*)&u2.x), b2 = __half22float2(*(__half2*)&u2.y);
        float2 a3 = __half22float2(*(__half2*)&u3.x), b3 = __half22float2(*(__half2*)&u3.y);
        acc.x += c0 * a0.x + c1 * a1.x + c2 * a2.x + c3 * a3.x;
        acc.y += c0 * a0.y + c1 * a1.y + c2 * a2.y + c3 * a3.y;
        acc.z += c0 * b0.x + c1 * b1.x + c2 * b2.x + c3 * b3.x;
        acc.w += c0 * b0.y + c1 * b1.y + c2 * b2.y + c3 * b3.y;
    }
    for (; e < end; e++) {
        int s = g_csr_src[e];
        float c = g_inv[s];
        uint2 u = ((const uint2*)(g_yh + (size_t)s * D))[lane];
        float2 a = __half22float2(*(__half2*)&u.x);
        float2 bb = __half22float2(*(__half2*)&u.y);
        acc.x += c * a.x; acc.y += c * a.y; acc.z += c * bb.x; acc.w += c * bb.y;
    }

    float invd = g_inv[w];
    float degf = (float)g_deg[w];
    float4 bv = ((const float4*)b)[lane];
    float4 o;
    o.x = invd * acc.x + degf * bv.x;
    o.y = invd * acc.y + degf * bv.y;
    o.z = invd * acc.z + degf * bv.z;
    o.w = invd * acc.w + degf * bv.w;
    ((float4*)(out + (size_t)w * D))[lane] = o;
}

extern "C" void kernel_launch(void* const* d_in, const int* in_sizes, int n_in,
                              void* d_out, int out_size) {
    const float* x   = (const float*)d_in[0];
    const void*  src = d_in[1];
    const void*  dst = d_in[2];
    const float* W   = (const float*)d_in[3];
    const float* b   = (const float*)d_in[4];
    float* out = (float*)d_out;

    (void)in_sizes; (void)n_in; (void)out_size;

    k_main<<<NB, 256>>>(x, src, dst, W);
    k_agg<<<(N_NODES * 32 + 255) / 256, 256>>>(b, out);
}